// round 3
// baseline (speedup 1.0000x reference)
#include <cuda_runtime.h>
#include <cstdint>

// out[b,j,h] = (1/N) * sum_i sum_g W[b,i,j,h,g] * x[b,i,g]
// B=16, N=32, H=64. W: 256 MiB fp32 streamed once -> pure HBM-bound.
//
// R3: TMA (cp.async.bulk 1D) 4-stage smem pipeline. One CTA per (b,j).
// tid0 produces 16KB tiles W[b,i,j,:,:] into smem ring; 256 threads consume.
// In-flight bytes/SM = 3 CTAs * 4 stages * 16KB = 192KB, independent of regs.

#define BB 16
#define NN 32
#define HH 64
#define STAGES 4
#define TILE_F4 1024              // HH*HH/4 floats4 = 16KB
#define TILE_BYTES 16384

__device__ __forceinline__ uint32_t smem_u32(const void* p) {
    return (uint32_t)__cvta_generic_to_shared(p);
}
__device__ __forceinline__ void mbar_init(uint32_t a, uint32_t count) {
    asm volatile("mbarrier.init.shared.b64 [%0], %1;" :: "r"(a), "r"(count) : "memory");
}
__device__ __forceinline__ void mbar_expect_tx(uint32_t a, uint32_t bytes) {
    asm volatile("mbarrier.arrive.expect_tx.shared.b64 _, [%0], %1;" :: "r"(a), "r"(bytes) : "memory");
}
__device__ __forceinline__ void mbar_arrive(uint32_t a) {
    asm volatile("mbarrier.arrive.shared.b64 _, [%0];" :: "r"(a) : "memory");
}
__device__ __forceinline__ void mbar_wait(uint32_t a, uint32_t parity) {
    asm volatile(
        "{\n\t.reg .pred P;\n\t"
        "WL_%=:\n\t"
        "mbarrier.try_wait.parity.shared.b64 P, [%0], %1;\n\t"
        "@P bra WD_%=;\n\t"
        "bra WL_%=;\n\t"
        "WD_%=:\n\t}"
        :: "r"(a), "r"(parity) : "memory");
}
__device__ __forceinline__ void bulk_g2s(uint32_t dst, const void* src,
                                         uint32_t bytes, uint32_t mbar) {
    asm volatile(
        "cp.async.bulk.shared::cta.global.mbarrier::complete_tx::bytes [%0], [%1], %2, [%3];"
        :: "r"(dst), "l"(src), "r"(bytes), "r"(mbar) : "memory");
}
__device__ __forceinline__ void fence_async_smem() {
    asm volatile("fence.proxy.async.shared::cta;" ::: "memory");
}

__global__ __launch_bounds__(256)
void msg_nn_kernel(const float4* __restrict__ W,
                   const float4* __restrict__ X,
                   float* __restrict__ out)
{
    extern __shared__ unsigned char smem_raw[];
    float4*  tiles = (float4*)smem_raw;                 // STAGES*1024 f4 = 64KB
    float4*  xs    = tiles + STAGES * TILE_F4;          // 512 f4 = 8KB
    uint64_t* mb   = (uint64_t*)(xs + NN * HH / 4);     // 2*STAGES barriers

    const uint32_t mb_base = smem_u32(mb);
    const uint32_t tiles_base = smem_u32(tiles);
    // full(s) = mb_base + s*16 ; empty(s) = mb_base + s*16 + 8

    const int bj = blockIdx.x;          // 0..511
    const int b  = bj >> 5;
    const int j  = bj & (NN - 1);
    const int t  = threadIdx.x;         // 0..255

    const size_t IS = (size_t)NN * TILE_F4;       // 32768 f4 per i
    const float4* Wbase = W + ((size_t)b * NN * NN + j) * TILE_F4;

    if (t == 0) {
        #pragma unroll
        for (int s = 0; s < STAGES; ++s) {
            mbar_init(mb_base + s * 16, 1);        // full: tx-based
            mbar_init(mb_base + s * 16 + 8, 256);  // empty: all threads arrive
        }
        fence_async_smem();
    }
    __syncthreads();

    // Stage x[b,:,:] into smem (512 float4)
    const float4* xb = X + (size_t)b * (NN * HH / 4);
    xs[t]       = xb[t];
    xs[t + 256] = xb[t + 256];

    // Prologue: issue first STAGES tiles
    if (t == 0) {
        #pragma unroll
        for (int s = 0; s < STAGES; ++s) {
            mbar_expect_tx(mb_base + s * 16, TILE_BYTES);
            bulk_g2s(tiles_base + s * TILE_BYTES, Wbase + (size_t)s * IS,
                     TILE_BYTES, mb_base + s * 16);
        }
    }
    __syncthreads();   // xs visible to all before consumption

    const int g4 = t & 15;
    const int h0 = t >> 4;

    float acc0 = 0.f, acc1 = 0.f, acc2 = 0.f, acc3 = 0.f;

    for (int i = 0; i < NN; ++i) {
        const int s  = i & (STAGES - 1);
        const uint32_t ph = (i >> 2) & 1;      // i/STAGES parity
        const uint32_t full_b  = mb_base + s * 16;
        const uint32_t empty_b = full_b + 8;

        mbar_wait(full_b, ph);

        const float4* tp = tiles + s * TILE_F4;
        const float4 xv = xs[i * 16 + g4];
        const float4 w0 = tp[t];
        const float4 w1 = tp[t + 256];
        const float4 w2 = tp[t + 512];
        const float4 w3 = tp[t + 768];

        acc0 += w0.x * xv.x + w0.y * xv.y + w0.z * xv.z + w0.w * xv.w;
        acc1 += w1.x * xv.x + w1.y * xv.y + w1.z * xv.z + w1.w * xv.w;
        acc2 += w2.x * xv.x + w2.y * xv.y + w2.z * xv.z + w2.w * xv.w;
        acc3 += w3.x * xv.x + w3.y * xv.y + w3.z * xv.z + w3.w * xv.w;

        mbar_arrive(empty_b);

        if (t == 0 && i + STAGES < NN) {
            mbar_wait(empty_b, ph);            // all 256 consumed this stage
            mbar_expect_tx(full_b, TILE_BYTES);
            bulk_g2s(tiles_base + s * TILE_BYTES,
                     Wbase + (size_t)(i + STAGES) * IS,
                     TILE_BYTES, full_b);
        }
    }

    // Reduce 16 g-quads per h within each contiguous 16-lane group.
    const unsigned mask = 0xFFFFFFFFu;
    #pragma unroll
    for (int off = 8; off > 0; off >>= 1) {
        acc0 += __shfl_down_sync(mask, acc0, off);
        acc1 += __shfl_down_sync(mask, acc1, off);
        acc2 += __shfl_down_sync(mask, acc2, off);
        acc3 += __shfl_down_sync(mask, acc3, off);
    }

    if (g4 == 0) {
        const float sc = 1.0f / (float)NN;
        float* o = out + (size_t)bj * HH + h0;
        o[0]  = acc0 * sc;
        o[16] = acc1 * sc;
        o[32] = acc2 * sc;
        o[48] = acc3 * sc;
    }
}

extern "C" void kernel_launch(void* const* d_in, const int* in_sizes, int n_in,
                              void* d_out, int out_size)
{
    const float4* W = (const float4*)d_in[0];   // edge_wgt [B,N,N,H,H] fp32
    const float4* X = (const float4*)d_in[1];   // node_hidden [B,N,H] fp32
    float* out = (float*)d_out;                 // [B,N,H] fp32

    const int smem_bytes = STAGES * TILE_BYTES          // tiles: 64KB
                         + (NN * HH / 4) * 16           // xs: 8KB
                         + 2 * STAGES * 8;              // barriers
    cudaFuncSetAttribute(msg_nn_kernel,
                         cudaFuncAttributeMaxDynamicSharedMemorySize, smem_bytes);

    msg_nn_kernel<<<BB * NN, 256, smem_bytes>>>(W, X, out);
}